// round 16
// baseline (speedup 1.0000x reference)
#include <cuda_runtime.h>

#define AN 76725
#define NC 80
#define CA (AN * NC)
#define CA4 (CA / 4)
#define NTIER 3
#define NSUB 32
#define SUBCAP 128
#define TIERCAP (NSUB * SUBCAP)
#define SKEYN 2048
#define MAXKEEP 200
#define IMGF 640.0f
#define T_A 0.9963f
#define T_B 0.99f
#define T_C 0.97f
#define NT 1024
#define NB 64
#define GRID 148
#define CH 16384  /* float4 per fill chunk = 1024 thr x 16 */
#define FULLW 0xFFFFFFFFu

// Scratch (device globals; zero-initialized at load; counters/cursor/barrier
// re-zeroed by scatter_kernel each call -> deterministic replay state)
__device__ float g_boxes[AN * 4];
__device__ float g_area[AN];
__device__ unsigned long long g_cand[NTIER][NC][TIERCAP];
__device__ int g_cntp[NSUB][NTIER][NC];
__device__ int g_bar, g_fillcur;
__device__ int g_kcnt[NC];
__device__ float4 g_kboxg[NC][MAXKEEP];
__device__ float g_kscg[NC][MAXKEEP];
__device__ int g_kidg[NC][MAXKEEP];

__device__ __forceinline__ float4 fill_val4(int i) {
    float v = (i >= CA4 && i < 2 * CA4) ? -1.0f : 0.0f;
    return make_float4(v, v, v, v);
}

// ---------------------------------------------------------------------------
// Persistent kernel: grid == 148 (one block per SM, all co-resident).
// Phase 1 (all blocks): decode + gather. Arrive at global barrier.
// Phase 2: blocks [0,80) NMS (fill-while-waiting on the barrier);
//          blocks [80,148) fill immediately. Everyone drains the fill cursor.
// ---------------------------------------------------------------------------
__global__ __launch_bounds__(NT, 1) void persist_kernel(
    const float* __restrict__ cls, const float* __restrict__ anchors,
    const float* __restrict__ reg, float4* __restrict__ out4, int n4) {
    const int tid = threadIdx.x;
    const int lane = tid & 31, wid = tid >> 5;
    const int gt = blockIdx.x * NT + tid;

    __shared__ int s_go, s_chunk;
    __shared__ unsigned long long skey[SKEYN];  // 16KB (fallback: supp bitmap)
    __shared__ unsigned long long cmask64[NB];
    __shared__ float4 bbox[NB];
    __shared__ float bar_[NB], bsc[NB];
    __shared__ int bidx[NB];
    __shared__ float4 kbox[MAXKEEP];
    __shared__ float kar[MAXKEEP], ksc[MAXKEEP];
    __shared__ int kid[MAXKEEP];
    __shared__ unsigned confParts[32];
    __shared__ unsigned long long km64_s;
    __shared__ unsigned long long red32[32];
    __shared__ int kcount;
    __shared__ int s_cnts[NTIER][NSUB];

    unsigned* cmW = (unsigned*)cmask64;

    // ---------------- phase 1: decode + gather ----------------
    if (gt < AN) {
        int i = gt;
        float a0 = anchors[i * 4 + 0], a1 = anchors[i * 4 + 1];
        float a2 = anchors[i * 4 + 2], a3 = anchors[i * 4 + 3];
        float r0 = reg[i * 4 + 0], r1 = reg[i * 4 + 1];
        float r2 = reg[i * 4 + 2], r3 = reg[i * 4 + 3];
        float aw = a2 - a0, ah = a3 - a1;
        float ax = a0 + 0.5f * aw, ay = a1 + 0.5f * ah;
        float cx = ax + r0 * 0.1f * aw;
        float cy = ay + r1 * 0.1f * ah;
        float w = aw * expf(r2 * 0.2f);
        float h = ah * expf(r3 * 0.2f);
        float x1 = fminf(fmaxf(cx - 0.5f * w, 0.0f), IMGF);
        float y1 = fminf(fmaxf(cy - 0.5f * h, 0.0f), IMGF);
        float x2 = fminf(fmaxf(cx + 0.5f * w, 0.0f), IMGF);
        float y2 = fminf(fmaxf(cy + 0.5f * h, 0.0f), IMGF);
        g_boxes[i * 4 + 0] = x1;
        g_boxes[i * 4 + 1] = y1;
        g_boxes[i * 4 + 2] = x2;
        g_boxes[i * 4 + 3] = y2;
        g_area[i] = (x2 - x1) * (y2 - y1);
    }

    {
        int sub = (blockIdx.x + wid) & (NSUB - 1);
        #pragma unroll 2
        for (int q = gt; q < CA4; q += GRID * NT) {
            float4 v = ((const float4*)cls)[q];
            if (fmaxf(fmaxf(v.x, v.y), fmaxf(v.z, v.w)) > T_C) {
                int f = q * 4;
                int a = f / NC;
                int c0 = f - a * NC;  // quad never crosses a row (NC%4==0)
                float sv[4] = {v.x, v.y, v.z, v.w};
                #pragma unroll
                for (int k = 0; k < 4; k++) {
                    float s = sv[k];
                    if (s > T_C) {
                        int tier = (s > T_A) ? 0 : ((s > T_B) ? 1 : 2);
                        int p = atomicAdd(&g_cntp[sub][tier][c0 + k], 1);
                        if (p < SUBCAP)
                            g_cand[tier][c0 + k][sub * SUBCAP + p] =
                                ((unsigned long long)__float_as_uint(s) << 32) |
                                (unsigned long long)(0xFFFFFFFFu - (unsigned)a);
                    }
                }
            }
        }
    }

    // arrive at global barrier (release: fence before counted arrival)
    __threadfence();
    __syncthreads();
    if (tid == 0) atomicAdd(&g_bar, 1);

    if (blockIdx.x < NC) {
        // ------------- fill while waiting for all gathers -------------
        for (;;) {
            if (tid == 0) {
                int done = (*(volatile int*)&g_bar) >= GRID;
                s_go = done;
                s_chunk = done ? 0 : atomicAdd(&g_fillcur, 1);
            }
            __syncthreads();
            if (s_go) break;
            int c0 = s_chunk * CH;
            if (c0 < n4) {
                int end = min(c0 + CH, n4);
                for (int i = c0 + tid; i < end; i += NT) out4[i] = fill_val4(i);
            } else if (tid == 0) {
                __nanosleep(500);
            }
            __syncthreads();
        }
        __threadfence();  // acquire side

        // ---------------- NMS for class c ----------------
        const int c = blockIdx.x;

        if (tid < NSUB * NTIER) {
            int s2 = tid / NTIER, tr = tid - s2 * NTIER;
            s_cnts[tr][s2] = g_cntp[s2][tr][c];
        }
        if (tid == 0) kcount = 0;
        __syncthreads();

        bool ok = true;
        for (int tier = 0; tier < NTIER; tier++) {
            if (kcount >= MAXKEEP) break;

            int n = 0;
            bool of = false;
            for (int s2 = 0; s2 < NSUB; s2++) {
                int cs = s_cnts[tier][s2];
                if (cs > SUBCAP) of = true;
                cs = min(cs, SUBCAP);
                for (int i = tid; i < cs; i += NT)
                    skey[min(n + i, SKEYN - 1)] = g_cand[tier][c][s2 * SUBCAP + i];
                n += cs;
            }
            if (of || n > SKEYN) { ok = false; break; }
            if (n == 0) continue;

            // ---- pad to m (>=64) + hybrid bitonic sort descending ----
            int m = 64;
            while (m < n) m <<= 1;
            for (int i = n + tid; i < m; i += NT) skey[i] = 0ULL;
            __syncthreads();

            for (int span = wid; span < (m >> 5); span += 32) {
                int e = span * 32 + lane;
                unsigned long long v = skey[e];
                #pragma unroll
                for (int k = 2; k <= 32; k <<= 1) {
                    bool d = ((e & k) == 0);
                    #pragma unroll
                    for (int j = k >> 1; j >= 1; j >>= 1) {
                        unsigned long long vp = __shfl_xor_sync(FULLW, v, j);
                        bool takeMax = (((e & j) == 0) == d);
                        v = takeMax ? (v > vp ? v : vp) : (v < vp ? v : vp);
                    }
                }
                skey[e] = v;
            }
            __syncthreads();

            for (int k = 64; k <= m; k <<= 1) {
                for (int j = k >> 1; j >= 32; j >>= 1) {
                    for (int i = tid; i < m; i += NT) {
                        int ixj = i ^ j;
                        if (ixj > i) {
                            bool desc = ((i & k) == 0);
                            unsigned long long A = skey[i], B2 = skey[ixj];
                            if (desc ? (A < B2) : (A > B2)) { skey[i] = B2; skey[ixj] = A; }
                        }
                    }
                    __syncthreads();
                }
                for (int span = wid; span < (m >> 5); span += 32) {
                    int e = span * 32 + lane;
                    unsigned long long v = skey[e];
                    bool d = ((e & k) == 0);
                    #pragma unroll
                    for (int j = 16; j >= 1; j >>= 1) {
                        unsigned long long vp = __shfl_xor_sync(FULLW, v, j);
                        bool takeMax = (((e & j) == 0) == d);
                        v = takeMax ? (v > vp ? v : vp) : (v < vp ? v : vp);
                    }
                    skey[e] = v;
                }
                __syncthreads();
            }

            // ---- batched walk, NB=64, 4 barriers/batch ----
            for (int base = 0; base < n; base += NB) {
                if (kcount >= MAXKEEP) break;
                int nb = min(NB, n - base);

                if (tid < nb) {
                    unsigned long long key = skey[base + tid];
                    float s = __uint_as_float((unsigned)(key >> 32));
                    int idx = (int)(0xFFFFFFFFu - (unsigned)key);
                    float4 bb;
                    bb.x = g_boxes[idx * 4 + 0];
                    bb.y = g_boxes[idx * 4 + 1];
                    bb.z = g_boxes[idx * 4 + 2];
                    bb.w = g_boxes[idx * 4 + 3];
                    bbox[tid] = bb;
                    bar_[tid] = g_area[idx];
                    bsc[tid] = s;
                    bidx[tid] = idx;
                }
                __syncthreads();  // B1

                int i = tid & 63;
                int g = tid >> 6;  // 0..15
                bool have = i < nb;
                float4 mb = make_float4(0, 0, 0, 0);
                float ma = 0;
                if (have) { mb = bbox[i]; ma = bar_[i]; }

                int kc = kcount;
                bool cfk = false;
                if (have) {
                    for (int j = g; j < kc; j += 16) {
                        float4 kb = kbox[j];
                        float ix1 = fmaxf(kb.x, mb.x), iy1 = fmaxf(kb.y, mb.y);
                        float ix2 = fminf(kb.z, mb.z), iy2 = fminf(kb.w, mb.w);
                        float inter = fmaxf(ix2 - ix1, 0.0f) * fmaxf(iy2 - iy1, 0.0f);
                        if (inter > 0.0f) {
                            float iou = inter / ((kar[j] + ma) - inter);
                            if (iou > 0.5f) { cfk = true; break; }
                        }
                    }
                }
                unsigned cb = __ballot_sync(FULLW, cfk);
                if (lane == 0) confParts[wid] = cb;

                for (int jb = 0; jb < nb; jb += 16) {
                    int j = jb + g;
                    bool cf = false;
                    if (have && j < nb && i != j) {
                        float4 jb4 = bbox[j];
                        float ja = bar_[j];
                        float ix1 = fmaxf(jb4.x, mb.x), iy1 = fmaxf(jb4.y, mb.y);
                        float ix2 = fminf(jb4.z, mb.z), iy2 = fminf(jb4.w, mb.w);
                        float inter = fmaxf(ix2 - ix1, 0.0f) * fmaxf(iy2 - iy1, 0.0f);
                        if (inter > 0.0f) {
                            float iou = inter / ((ja + ma) - inter);
                            cf = iou > 0.5f;
                        }
                    }
                    unsigned bits = __ballot_sync(FULLW, cf);
                    if (lane == 0 && j < nb) cmW[2 * j + (wid & 1)] = bits;
                }
                __syncthreads();  // B2

                if (wid == 0) {
                    unsigned v = confParts[lane];
                    unsigned evenOr = __reduce_or_sync(FULLW, (lane & 1) ? 0u : v);
                    unsigned oddOr = __reduce_or_sync(FULLW, (lane & 1) ? v : 0u);
                    unsigned long long conf = ((unsigned long long)oddOr << 32) | evenOr;
                    unsigned long long hv = (nb >= 64) ? ~0ULL : ((1ULL << nb) - 1ULL);
                    unsigned long long alive64 = hv & ~conf;

                    int q0 = lane, q1 = lane + 32;
                    bool a0v = (alive64 >> q0) & 1ULL;
                    bool a1v = (alive64 >> q1) & 1ULL;
                    unsigned long long r0 = a0v ? cmask64[q0] : 0ULL;
                    unsigned long long r1 = a1v ? cmask64[q1] : 0ULL;
                    bool t0b = a0v && ((r0 & alive64 & ((1ULL << q0) - 1ULL)) == 0ULL);
                    bool t1b = a1v && ((r1 & alive64 & ((1ULL << q1) - 1ULL)) == 0ULL);
                    bool d0b = a0v && !t0b;
                    bool d1b = a1v && !t1b;
                    unsigned bt0 = __ballot_sync(FULLW, t0b);
                    unsigned bt1 = __ballot_sync(FULLW, t1b);
                    unsigned bd0 = __ballot_sync(FULLW, d0b);
                    unsigned bd1 = __ballot_sync(FULLW, d1b);
                    if (lane == 0) {
                        unsigned long long kw = ((unsigned long long)bt1 << 32) | bt0;
                        unsigned long long dbits = ((unsigned long long)bd1 << 32) | bd0;
                        while (dbits) {
                            int q = __ffsll((long long)dbits) - 1;
                            dbits &= dbits - 1ULL;
                            unsigned long long below = (1ULL << q) - 1ULL;
                            if ((cmask64[q] & kw & below) == 0ULL) kw |= (1ULL << q);
                        }
                        int rem = MAXKEEP - kc;
                        int p = __popcll(kw);
                        while (p > rem) {
                            kw &= ~(0x8000000000000000ULL >> __clzll((long long)kw));
                            p--;
                        }
                        km64_s = kw;
                    }
                }
                __syncthreads();  // B3

                unsigned long long kw = km64_s;
                int kc0 = kcount;
                if (tid < 64 && ((kw >> tid) & 1ULL)) {
                    int pos = kc0 + __popcll(kw & ((1ULL << tid) - 1ULL));
                    kbox[pos] = bbox[tid];
                    kar[pos] = bar_[tid];
                    ksc[pos] = bsc[tid];
                    kid[pos] = bidx[tid];
                }
                if (tid == 0) kcount = kc0 + __popcll(kw);
                __syncthreads();  // B4
            }
        }
        __syncthreads();

        // ---- Exact fallback (never triggered for this data) ----
        if (!ok || kcount < MAXKEEP) {
            unsigned* supp = (unsigned*)skey;
            const int NW = (AN + 31) / 32;
            for (int w2 = tid; w2 < NW; w2 += NT) supp[w2] = 0u;
            if (tid == 0) kcount = 0;
            __syncthreads();
            for (int it = 0; it < MAXKEEP; it++) {
                unsigned long long best = 0ULL;
                for (int i = tid; i < AN; i += NT) {
                    if (!((supp[i >> 5] >> (i & 31)) & 1u)) {
                        float s = cls[i * NC + c];
                        if (s > 0.1f) {
                            unsigned long long k =
                                ((unsigned long long)__float_as_uint(s) << 32) |
                                (unsigned long long)(0xFFFFFFFFu - (unsigned)i);
                            if (k > best) best = k;
                        }
                    }
                }
                #pragma unroll
                for (int off = 16; off > 0; off >>= 1) {
                    unsigned long long o = __shfl_down_sync(FULLW, best, off);
                    if (o > best) best = o;
                }
                if (lane == 0) red32[wid] = best;
                __syncthreads();
                if (tid == 0) {
                    unsigned long long b2 = red32[0];
                    for (int w = 1; w < 32; w++)
                        if (red32[w] > b2) b2 = red32[w];
                    red32[0] = b2;
                }
                __syncthreads();
                unsigned long long bk = red32[0];
                __syncthreads();
                if (bk == 0ULL) break;
                int bi = (int)(0xFFFFFFFFu - (unsigned)bk);
                float s = __uint_as_float((unsigned)(bk >> 32));
                float zx1 = g_boxes[bi * 4 + 0], zy1 = g_boxes[bi * 4 + 1];
                float zx2 = g_boxes[bi * 4 + 2], zy2 = g_boxes[bi * 4 + 3];
                float za = g_area[bi];
                if (tid == 0) {
                    int kc2 = kcount;
                    kbox[kc2] = make_float4(zx1, zy1, zx2, zy2);
                    kar[kc2] = za; ksc[kc2] = s; kid[kc2] = bi;
                    kcount = kc2 + 1;
                }
                for (int i = tid; i < AN; i += NT) {
                    float ix1 = fmaxf(zx1, g_boxes[i * 4 + 0]);
                    float iy1 = fmaxf(zy1, g_boxes[i * 4 + 1]);
                    float ix2 = fminf(zx2, g_boxes[i * 4 + 2]);
                    float iy2 = fminf(zy2, g_boxes[i * 4 + 3]);
                    float inter = fmaxf(ix2 - ix1, 0.0f) * fmaxf(iy2 - iy1, 0.0f);
                    float iou = inter / ((za + g_area[i]) - inter);
                    if (iou > 0.5f || i == bi) atomicOr(&supp[i >> 5], 1u << (i & 31));
                }
                __syncthreads();
            }
            __syncthreads();
        }

        // ---- write compact results ----
        int kc = kcount;
        if (tid == 0) g_kcnt[c] = kc;
        for (int t = tid; t < kc; t += NT) {
            g_kboxg[c][t] = kbox[t];
            g_kscg[c][t] = ksc[t];
            g_kidg[c][t] = kid[t];
        }
        // fall through: join the fill cursor
    }

    // ---------------- drain the fill cursor (all blocks) ----------------
    for (;;) {
        if (tid == 0) s_chunk = atomicAdd(&g_fillcur, 1);
        __syncthreads();
        int c0 = s_chunk * CH;
        if (c0 >= n4) break;
        int end = min(c0 + CH, n4);
        for (int i = c0 + tid; i < end; i += NT) out4[i] = fill_val4(i);
        __syncthreads();
    }
}

// ---------------------------------------------------------------------------
// Scatter: 1 thread per (class, slot); also resets all replay state.
// ---------------------------------------------------------------------------
__global__ void scatter_kernel(float* __restrict__ out) {
    int flat = blockIdx.x * blockDim.x + threadIdx.x;
    if (flat < NSUB * NTIER * NC) ((int*)g_cntp)[flat] = 0;
    if (flat == NSUB * NTIER * NC) { g_bar = 0; g_fillcur = 0; }
    if (flat >= NC * MAXKEEP) return;
    int c = flat / MAXKEEP;
    int t = flat - c * MAXKEEP;
    if (t >= g_kcnt[c]) return;
    int i = g_kidg[c][t];
    out[c * AN + i] = g_kscg[c][t];
    out[CA + c * AN + i] = (float)c;
    ((float4*)(out + 2 * CA))[c * AN + i] = g_kboxg[c][t];
    out[6 * CA + c * AN + i] = 1.0f;
}

// ---------------------------------------------------------------------------
extern "C" void kernel_launch(void* const* d_in, const int* in_sizes, int n_in,
                              void* d_out, int out_size) {
    const float* classification = (const float*)d_in[0];  // [1, A, C]
    const float* regression = (const float*)d_in[1];      // [1, A, 4]
    const float* anchors = (const float*)d_in[2];         // [A, 4]
    float* out = (float*)d_out;

    int n4 = out_size / 4;
    persist_kernel<<<GRID, NT>>>(classification, anchors, regression,
                                 (float4*)out, n4);
    scatter_kernel<<<(NC * MAXKEEP + 255) / 256, 256>>>(out);
}

// round 17
// speedup vs baseline: 1.0359x; 1.0359x over previous
#include <cuda_runtime.h>

#define AN 76725
#define NC 80
#define CA (AN * NC)
#define CA4 (CA / 4)
#define NTIER 3
#define NSUB 32
#define SUBCAP 128
#define TIERCAP (NSUB * SUBCAP)
#define SKEYN 2048
#define MAXKEEP 200
#define IMGF 640.0f
#define T_A 0.9963f
#define T_B 0.99f
#define T_C 0.97f
#define NT 1024
#define NB 64
#define GPREP 1499
#define FILLB 68
#define CH2 (NT * 16)    /* K2 fill chunk: 1024 thr x 16 float4 */
#define FULLW 0xFFFFFFFFu

// Scratch (device globals; zero-initialized at load, counters/cursor
// re-zeroed by scatter_kernel at the end of every call)
__device__ float g_boxes[AN * 4];
__device__ float g_area[AN];
__device__ unsigned long long g_cand[NTIER][NC][TIERCAP];
__device__ int g_cntp[NSUB][NTIER][NC];
__device__ int g_fillcurB;
__device__ int g_kcnt[NC];
__device__ float4 g_kboxg[NC][MAXKEEP];
__device__ float g_kscg[NC][MAXKEEP];
__device__ int g_kidg[NC][MAXKEEP];

__device__ __forceinline__ float4 fill_val4(int i) {
    float v = (i >= CA4 && i < 2 * CA4) ? -1.0f : 0.0f;
    return make_float4(v, v, v, v);
}

__device__ __forceinline__ void gather_quad(float4 v, int q, int sub) {
    if (fmaxf(fmaxf(v.x, v.y), fmaxf(v.z, v.w)) > T_C) {
        int f = q * 4;
        int a = f / NC;       // quad never crosses a row (NC % 4 == 0)
        int c0 = f - a * NC;
        float sv[4] = {v.x, v.y, v.z, v.w};
        #pragma unroll
        for (int k = 0; k < 4; k++) {
            float s = sv[k];
            if (s > T_C) {
                int tier = (s > T_A) ? 0 : ((s > T_B) ? 1 : 2);
                int p = atomicAdd(&g_cntp[sub][tier][c0 + k], 1);
                if (p < SUBCAP)
                    g_cand[tier][c0 + k][sub * SUBCAP + p] =
                        ((unsigned long long)__float_as_uint(s) << 32) |
                        (unsigned long long)(0xFFFFFFFFu - (unsigned)a);
            }
        }
    }
}

// ---------------------------------------------------------------------------
// K1: gather + decode, with fill-A stores interleaved into the gather load
// shadow (static per-thread fill slice; stores are independent of the loads).
// ---------------------------------------------------------------------------
__global__ __launch_bounds__(256) void prep_kernel(const float* __restrict__ cls,
                                                   const float* __restrict__ anchors,
                                                   const float* __restrict__ reg,
                                                   float4* __restrict__ out4,
                                                   int split4) {
    int t = blockIdx.x * blockDim.x + threadIdx.x;
    const int stride = GPREP * 256;
    int sub = (blockIdx.x * 8 + (threadIdx.x >> 5)) & (NSUB - 1);

    // decode duty for the first AN threads
    if (t < AN) {
        int i = t;
        float a0 = anchors[i * 4 + 0], a1 = anchors[i * 4 + 1];
        float a2 = anchors[i * 4 + 2], a3 = anchors[i * 4 + 3];
        float r0 = reg[i * 4 + 0], r1 = reg[i * 4 + 1];
        float r2 = reg[i * 4 + 2], r3 = reg[i * 4 + 3];
        float aw = a2 - a0, ah = a3 - a1;
        float ax = a0 + 0.5f * aw, ay = a1 + 0.5f * ah;
        float cx = ax + r0 * 0.1f * aw;
        float cy = ay + r1 * 0.1f * ah;
        float w = aw * expf(r2 * 0.2f);
        float h = ah * expf(r3 * 0.2f);
        float x1 = fminf(fmaxf(cx - 0.5f * w, 0.0f), IMGF);
        float y1 = fminf(fmaxf(cy - 0.5f * h, 0.0f), IMGF);
        float x2 = fminf(fmaxf(cx + 0.5f * w, 0.0f), IMGF);
        float y2 = fminf(fmaxf(cy + 0.5f * h, 0.0f), IMGF);
        g_boxes[i * 4 + 0] = x1;
        g_boxes[i * 4 + 1] = y1;
        g_boxes[i * 4 + 2] = x2;
        g_boxes[i * 4 + 3] = y2;
        g_area[i] = (x2 - x1) * (y2 - y1);
    }

    // issue the 4 gather loads up front
    int q0 = t, q1 = t + stride, q2 = t + 2 * stride, q3 = t + 3 * stride;
    bool b0 = q0 < CA4, b1 = q1 < CA4, b2 = q2 < CA4, b3 = q3 < CA4;
    float4 v0 = make_float4(0, 0, 0, 0), v1 = v0, v2 = v0, v3 = v0;
    if (b0) v0 = ((const float4*)cls)[q0];
    if (b1) v1 = ((const float4*)cls)[q1];
    if (b2) v2 = ((const float4*)cls)[q2];
    if (b3) v3 = ((const float4*)cls)[q3];

    // fill-A: independent stores executed in the load shadow
    for (int i = t; i < split4; i += stride) out4[i] = fill_val4(i);

    // consume the loads
    if (b0) gather_quad(v0, q0, sub);
    if (b1) gather_quad(v1, q1, sub);
    if (b2) gather_quad(v2, q2, sub);
    if (b3) gather_quad(v3, q3, sub);
}

// ---------------------------------------------------------------------------
// K3: flat scatter (1 thread per (class, slot)) + counter/cursor reset
// ---------------------------------------------------------------------------
__global__ void scatter_kernel(float* __restrict__ out) {
    int flat = blockIdx.x * blockDim.x + threadIdx.x;
    if (flat < NSUB * NTIER * NC) ((int*)g_cntp)[flat] = 0;
    if (flat == NSUB * NTIER * NC) g_fillcurB = 0;
    if (flat >= NC * MAXKEEP) return;
    int c = flat / MAXKEEP;
    int t = flat - c * MAXKEEP;
    if (t >= g_kcnt[c]) return;
    int i = g_kidg[c][t];
    out[c * AN + i] = g_kscg[c][t];
    out[CA + c * AN + i] = (float)c;
    ((float4*)(out + 2 * CA))[c * AN + i] = g_kboxg[c][t];
    out[6 * CA + c * AN + i] = 1.0f;
}

// ---------------------------------------------------------------------------
// K2: blocks [0, NC) per-class NMS (then join fill); blocks [NC, NC+FILLB)
// fill [split4, n4) via work-stealing cursor.  (R15-proven shape.)
// ---------------------------------------------------------------------------
__global__ __launch_bounds__(NT) void fused_kernel(const float* __restrict__ cls,
                                                   float4* __restrict__ out4,
                                                   int split4, int n4) {
    __shared__ int s_chunk;
    const int tid = threadIdx.x;
    const int lane = tid & 31, wid = tid >> 5;

    if (blockIdx.x < NC) {
        // ---------------- NMS path ----------------
        const int c = blockIdx.x;

        __shared__ unsigned long long skey[SKEYN];      // 16KB (fallback: supp bitmap)
        __shared__ unsigned long long cmask64[NB];
        __shared__ float4 bbox[NB];
        __shared__ float bar_[NB], bsc[NB];
        __shared__ int bidx[NB];
        __shared__ float4 kbox[MAXKEEP];
        __shared__ float kar[MAXKEEP], ksc[MAXKEEP];
        __shared__ int kid[MAXKEEP];
        __shared__ unsigned confParts[32];
        __shared__ unsigned long long km64_s;
        __shared__ unsigned long long red32[32];
        __shared__ int kcount;
        __shared__ int s_cnts[NTIER][NSUB];

        unsigned* cmW = (unsigned*)cmask64;

        // preload all 96 sub-counts in one parallel burst
        if (tid < NSUB * NTIER) {
            int s2 = tid / NTIER, tr = tid - s2 * NTIER;
            s_cnts[tr][s2] = g_cntp[s2][tr][c];
        }
        if (tid == 0) kcount = 0;
        __syncthreads();

        bool ok = true;
        for (int tier = 0; tier < NTIER; tier++) {
            if (kcount >= MAXKEEP) break;

            // concatenate the 32 sub-lists (counts in shared; loads pipeline)
            int n = 0;
            bool of = false;
            for (int s2 = 0; s2 < NSUB; s2++) {
                int cs = s_cnts[tier][s2];
                if (cs > SUBCAP) of = true;
                cs = min(cs, SUBCAP);
                for (int i = tid; i < cs; i += NT)
                    skey[min(n + i, SKEYN - 1)] = g_cand[tier][c][s2 * SUBCAP + i];
                n += cs;
            }
            if (of || n > SKEYN) { ok = false; break; }
            if (n == 0) continue;

            // ---- pad to m (>=64) + hybrid bitonic sort descending ----
            int m = 64;
            while (m < n) m <<= 1;
            for (int i = n + tid; i < m; i += NT) skey[i] = 0ULL;
            __syncthreads();

            // phase k=2..32 fully in registers (warp-local spans, no barriers)
            for (int span = wid; span < (m >> 5); span += 32) {
                int e = span * 32 + lane;
                unsigned long long v = skey[e];
                #pragma unroll
                for (int k = 2; k <= 32; k <<= 1) {
                    bool d = ((e & k) == 0);
                    #pragma unroll
                    for (int j = k >> 1; j >= 1; j >>= 1) {
                        unsigned long long vp = __shfl_xor_sync(FULLW, v, j);
                        bool takeMax = (((e & j) == 0) == d);
                        v = takeMax ? (v > vp ? v : vp) : (v < vp ? v : vp);
                    }
                }
                skey[e] = v;
            }
            __syncthreads();

            // phases k=64..m: shared steps for j>=32, fused shfl for j<=16
            for (int k = 64; k <= m; k <<= 1) {
                for (int j = k >> 1; j >= 32; j >>= 1) {
                    for (int i = tid; i < m; i += NT) {
                        int ixj = i ^ j;
                        if (ixj > i) {
                            bool desc = ((i & k) == 0);
                            unsigned long long A = skey[i], B2 = skey[ixj];
                            if (desc ? (A < B2) : (A > B2)) { skey[i] = B2; skey[ixj] = A; }
                        }
                    }
                    __syncthreads();
                }
                for (int span = wid; span < (m >> 5); span += 32) {
                    int e = span * 32 + lane;
                    unsigned long long v = skey[e];
                    bool d = ((e & k) == 0);
                    #pragma unroll
                    for (int j = 16; j >= 1; j >>= 1) {
                        unsigned long long vp = __shfl_xor_sync(FULLW, v, j);
                        bool takeMax = (((e & j) == 0) == d);
                        v = takeMax ? (v > vp ? v : vp) : (v < vp ? v : vp);
                    }
                    skey[e] = v;
                }
                __syncthreads();
            }

            // ---- batched walk, NB=64, 4 barriers/batch ----
            for (int base = 0; base < n; base += NB) {
                if (kcount >= MAXKEEP) break;
                int nb = min(NB, n - base);

                if (tid < nb) {
                    unsigned long long key = skey[base + tid];
                    float s = __uint_as_float((unsigned)(key >> 32));
                    int idx = (int)(0xFFFFFFFFu - (unsigned)key);
                    float4 bb;
                    bb.x = g_boxes[idx * 4 + 0];
                    bb.y = g_boxes[idx * 4 + 1];
                    bb.z = g_boxes[idx * 4 + 2];
                    bb.w = g_boxes[idx * 4 + 3];
                    bbox[tid] = bb;
                    bar_[tid] = g_area[idx];
                    bsc[tid] = s;
                    bidx[tid] = idx;
                }
                __syncthreads();  // B1

                int i = tid & 63;
                int g = tid >> 6;  // 0..15
                bool have = i < nb;
                float4 mb = make_float4(0, 0, 0, 0);
                float ma = 0;
                if (have) { mb = bbox[i]; ma = bar_[i]; }

                // phase 1a: conflict vs kept list, 16-way split per candidate
                int kc = kcount;
                bool cfk = false;
                if (have) {
                    for (int j = g; j < kc; j += 16) {
                        float4 kb = kbox[j];
                        float ix1 = fmaxf(kb.x, mb.x), iy1 = fmaxf(kb.y, mb.y);
                        float ix2 = fminf(kb.z, mb.z), iy2 = fminf(kb.w, mb.w);
                        float inter = fmaxf(ix2 - ix1, 0.0f) * fmaxf(iy2 - iy1, 0.0f);
                        if (inter > 0.0f) {
                            float iou = inter / ((kar[j] + ma) - inter);
                            if (iou > 0.5f) { cfk = true; break; }
                        }
                    }
                }
                unsigned cb = __ballot_sync(FULLW, cfk);
                if (lane == 0) confParts[wid] = cb;

                // phase 1b immediately (needs only bbox, synced at B1)
                for (int jb = 0; jb < nb; jb += 16) {
                    int j = jb + g;
                    bool cf = false;
                    if (have && j < nb && i != j) {
                        float4 jb4 = bbox[j];
                        float ja = bar_[j];
                        float ix1 = fmaxf(jb4.x, mb.x), iy1 = fmaxf(jb4.y, mb.y);
                        float ix2 = fminf(jb4.z, mb.z), iy2 = fminf(jb4.w, mb.w);
                        float inter = fmaxf(ix2 - ix1, 0.0f) * fmaxf(iy2 - iy1, 0.0f);
                        if (inter > 0.0f) {
                            float iou = inter / ((ja + ma) - inter);
                            cf = iou > 0.5f;
                        }
                    }
                    unsigned bits = __ballot_sync(FULLW, cf);
                    if (lane == 0 && j < nb) cmW[2 * j + (wid & 1)] = bits;
                }
                __syncthreads();  // B2

                // warp 0: alive + classify + resolve + truncate
                if (wid == 0) {
                    unsigned v = confParts[lane];
                    unsigned evenOr = __reduce_or_sync(FULLW, (lane & 1) ? 0u : v);
                    unsigned oddOr = __reduce_or_sync(FULLW, (lane & 1) ? v : 0u);
                    unsigned long long conf = ((unsigned long long)oddOr << 32) | evenOr;
                    unsigned long long hv = (nb >= 64) ? ~0ULL : ((1ULL << nb) - 1ULL);
                    unsigned long long alive64 = hv & ~conf;

                    int q0 = lane, q1 = lane + 32;
                    bool a0v = (alive64 >> q0) & 1ULL;
                    bool a1v = (alive64 >> q1) & 1ULL;
                    unsigned long long r0 = a0v ? cmask64[q0] : 0ULL;
                    unsigned long long r1 = a1v ? cmask64[q1] : 0ULL;
                    bool t0b = a0v && ((r0 & alive64 & ((1ULL << q0) - 1ULL)) == 0ULL);
                    bool t1b = a1v && ((r1 & alive64 & ((1ULL << q1) - 1ULL)) == 0ULL);
                    bool d0b = a0v && !t0b;
                    bool d1b = a1v && !t1b;
                    unsigned bt0 = __ballot_sync(FULLW, t0b);
                    unsigned bt1 = __ballot_sync(FULLW, t1b);
                    unsigned bd0 = __ballot_sync(FULLW, d0b);
                    unsigned bd1 = __ballot_sync(FULLW, d1b);
                    if (lane == 0) {
                        unsigned long long kw = ((unsigned long long)bt1 << 32) | bt0;
                        unsigned long long dbits = ((unsigned long long)bd1 << 32) | bd0;
                        while (dbits) {
                            int q = __ffsll((long long)dbits) - 1;
                            dbits &= dbits - 1ULL;
                            unsigned long long below = (1ULL << q) - 1ULL;
                            if ((cmask64[q] & kw & below) == 0ULL) kw |= (1ULL << q);
                        }
                        int rem = MAXKEEP - kc;
                        int p = __popcll(kw);
                        while (p > rem) {
                            kw &= ~(0x8000000000000000ULL >> __clzll((long long)kw));
                            p--;
                        }
                        km64_s = kw;
                    }
                }
                __syncthreads();  // B3

                unsigned long long kw = km64_s;
                int kc0 = kcount;
                if (tid < 64 && ((kw >> tid) & 1ULL)) {
                    int pos = kc0 + __popcll(kw & ((1ULL << tid) - 1ULL));
                    kbox[pos] = bbox[tid];
                    kar[pos] = bar_[tid];
                    ksc[pos] = bsc[tid];
                    kid[pos] = bidx[tid];
                }
                if (tid == 0) kcount = kc0 + __popcll(kw);
                __syncthreads();  // B4
            }
        }
        __syncthreads();

        // ---- Exact fallback (never triggered for this data) ----
        if (!ok || kcount < MAXKEEP) {
            unsigned* supp = (unsigned*)skey;
            const int NW = (AN + 31) / 32;
            for (int w2 = tid; w2 < NW; w2 += NT) supp[w2] = 0u;
            if (tid == 0) kcount = 0;
            __syncthreads();
            for (int it = 0; it < MAXKEEP; it++) {
                unsigned long long best = 0ULL;
                for (int i = tid; i < AN; i += NT) {
                    if (!((supp[i >> 5] >> (i & 31)) & 1u)) {
                        float s = cls[i * NC + c];
                        if (s > 0.1f) {
                            unsigned long long k =
                                ((unsigned long long)__float_as_uint(s) << 32) |
                                (unsigned long long)(0xFFFFFFFFu - (unsigned)i);
                            if (k > best) best = k;
                        }
                    }
                }
                #pragma unroll
                for (int off = 16; off > 0; off >>= 1) {
                    unsigned long long o = __shfl_down_sync(FULLW, best, off);
                    if (o > best) best = o;
                }
                if (lane == 0) red32[wid] = best;
                __syncthreads();
                if (tid == 0) {
                    unsigned long long b2 = red32[0];
                    for (int w = 1; w < 32; w++)
                        if (red32[w] > b2) b2 = red32[w];
                    red32[0] = b2;
                }
                __syncthreads();
                unsigned long long bk = red32[0];
                __syncthreads();
                if (bk == 0ULL) break;
                int bi = (int)(0xFFFFFFFFu - (unsigned)bk);
                float s = __uint_as_float((unsigned)(bk >> 32));
                float zx1 = g_boxes[bi * 4 + 0], zy1 = g_boxes[bi * 4 + 1];
                float zx2 = g_boxes[bi * 4 + 2], zy2 = g_boxes[bi * 4 + 3];
                float za = g_area[bi];
                if (tid == 0) {
                    int kc2 = kcount;
                    kbox[kc2] = make_float4(zx1, zy1, zx2, zy2);
                    kar[kc2] = za; ksc[kc2] = s; kid[kc2] = bi;
                    kcount = kc2 + 1;
                }
                for (int i = tid; i < AN; i += NT) {
                    float ix1 = fmaxf(zx1, g_boxes[i * 4 + 0]);
                    float iy1 = fmaxf(zy1, g_boxes[i * 4 + 1]);
                    float ix2 = fminf(zx2, g_boxes[i * 4 + 2]);
                    float iy2 = fminf(zy2, g_boxes[i * 4 + 3]);
                    float inter = fmaxf(ix2 - ix1, 0.0f) * fmaxf(iy2 - iy1, 0.0f);
                    float iou = inter / ((za + g_area[i]) - inter);
                    if (iou > 0.5f || i == bi) atomicOr(&supp[i >> 5], 1u << (i & 31));
                }
                __syncthreads();
            }
            __syncthreads();
        }

        // ---- write compact results ----
        int kc = kcount;
        if (tid == 0) g_kcnt[c] = kc;
        for (int t = tid; t < kc; t += NT) {
            g_kboxg[c][t] = kbox[t];
            g_kscg[c][t] = ksc[t];
            g_kidg[c][t] = kid[t];
        }
        // fall through: join fill-B below
    }

    // ---------------- fill-B (work-stealing; fill blocks + post-NMS blocks) --
    for (;;) {
        if (tid == 0) s_chunk = atomicAdd(&g_fillcurB, 1);
        __syncthreads();
        int c0 = split4 + s_chunk * CH2;
        if (c0 >= n4) break;
        int end = min(c0 + CH2, n4);
        for (int i = c0 + tid; i < end; i += NT) out4[i] = fill_val4(i);
        __syncthreads();
    }
}

// ---------------------------------------------------------------------------
extern "C" void kernel_launch(void* const* d_in, const int* in_sizes, int n_in,
                              void* d_out, int out_size) {
    const float* classification = (const float*)d_in[0];  // [1, A, C]
    const float* regression = (const float*)d_in[1];      // [1, A, 4]
    const float* anchors = (const float*)d_in[2];         // [A, 4]
    float* out = (float*)d_out;

    int n4 = out_size / 4;
    int split4 = (int)(((long long)n4 * 45) / 100);  // 45% of fill in K1

    prep_kernel<<<GPREP, 256>>>(classification, anchors, regression,
                                (float4*)out, split4);
    fused_kernel<<<NC + FILLB, NT>>>(classification, (float4*)out, split4, n4);
    scatter_kernel<<<(NC * MAXKEEP + 255) / 256, 256>>>(out);
}